// round 6
// baseline (speedup 1.0000x reference)
#include <cuda_runtime.h>
#include <math.h>

// Fixed problem shapes: b=8, n=4096, c=32, g=4, rad=4, rank=2, k=128, in=1024, OUT=1024
#define BB    8
#define CC    32
#define GG    4
#define RADR  4
#define KK    128
#define PPC   12          // 4 neighbor + 4 sampled + 4 range-restricted
#define NP    384         // CC * PPC points per (b,k) tile
#define INSZ  1024
#define OUTSZ 1024
#define NWARP 12          // NP/32
#define HSZ   1024        // dup-hash slots (power of 2)

// sqrt(0.5 * log2(e)) — folds the -0.5 and exp->exp2 into the inverse sigmas.
#define SQRT_HALF_LOG2E 0.8493218383f

__device__ __forceinline__ float ex2_approx(float v) {
    float r;
    asm("ex2.approx.f32 %0, %1;" : "=f"(r) : "f"(v));
    return r;
}

__global__ __launch_bounds__(NP) void sparse_layer_kernel(
    const float* __restrict__ x,        // (8, 1024)
    const float* __restrict__ means,    // (8, 4096, 2)
    const float* __restrict__ sigmas,   // (8, 4096, 2)
    const float* __restrict__ values,   // (8, 4096)
    const float* __restrict__ su,       // (8, 128, 32, 4, 2)
    const float* __restrict__ ru,       // (8, 128, 32, 4, 2)
    float* __restrict__ out)            // (8, 1024)
{
    __shared__ float  sm0[CC], sm1[CC];
    __shared__ float4 scell[CC];            // (v0, v1, m0*v0, m1*v1)
    __shared__ float  sval[CC], svalw[CC];
    __shared__ float2 spts[NP];             // (p0 or 1e30 if dup, p1)
    __shared__ float  spart[NWARP * CC];
    __shared__ unsigned int tab[HSZ];       // hash: (id<<9)|minidx, EMPTY=0xFFFFFFFF

    const int bk = blockIdx.x;              // b*128 + k
    const int b  = bk >> 7;
    const int t  = threadIdx.x;
    const int w  = t >> 5;
    const int l  = t & 31;

    // ---- init hash + load per-cell params ----
    #pragma unroll
    for (int i = t; i < HSZ; i += NP) tab[i] = 0xFFFFFFFFu;
    if (t < CC) {
        int base = (bk * CC + t) * 2;
        float m0 = means[base], m1 = means[base + 1];
        float v0 = sqrtf(1.0f / (1e-6f + sigmas[base]))     * SQRT_HALF_LOG2E;
        float v1 = sqrtf(1.0f / (1e-6f + sigmas[base + 1])) * SQRT_HALF_LOG2E;
        sm0[t] = m0;
        sm1[t] = m1;
        scell[t] = make_float4(v0, v1, m0 * v0, m1 * v1);
        sval[t] = values[bk * CC + t];
    }
    __syncthreads();

    // ---- generate integer tuple for this thread's point: cell c = t/12, slot j ----
    int id;
    {
        const int c = t / PPC;
        const int j = t - c * PPC;
        const float m0v = sm0[c], m1v = sm1[c];
        const float SCL = 1.0f - 1e-6f;
        int i0, i1;
        if (j < 4) {
            // fm order (itertools.product([T,F],2)): True->floor
            i0 = (j & 2) ? (int)ceilf(m0v) : (int)floorf(m0v);
            i1 = (j & 1) ? (int)ceilf(m1v) : (int)floorf(m1v);
        } else if (j < 8) {
            int idx = ((bk * CC + c) * GG + (j - 4)) * 2;
            i0 = (int)floorf(__fmul_rn(__fmul_rn(su[idx],     SCL), 1024.0f));
            i1 = (int)floorf(__fmul_rn(__fmul_rn(su[idx + 1], SCL), 1024.0f));
        } else {
            int idx = ((bk * CC + c) * RADR + (j - 8)) * 2;
            float mn0 = rintf(m0v), mn1 = rintf(m1v);   // round half-even (jnp.round)
            float lo0 = mn0 - 8.0f, lo1 = mn1 - 8.0f;
            if (lo0 < 0.0f) lo0 = 0.0f;
            if (mn0 + 8.0f > 1024.0f) lo0 = 1008.0f;
            if (lo1 < 0.0f) lo1 = 0.0f;
            if (mn1 + 8.0f > 1024.0f) lo1 = 1008.0f;
            i0 = (int)floorf(__fadd_rn(__fmul_rn(__fmul_rn(ru[idx],     SCL), 16.0f), lo0));
            i1 = (int)floorf(__fadd_rn(__fmul_rn(__fmul_rn(ru[idx + 1], SCL), 16.0f), lo1));
        }
        id = (i0 << 10) | i1;
    }

    // ---- duplicate marking via shared hash (first occurrence by thread index wins) ----
    bool dup;
    {
        const unsigned int uid = (unsigned int)id;
        const unsigned int val = (uid << 9) | (unsigned int)t;   // 20+9 bits < 2^29
        unsigned int h = (uid * 2654435761u) >> 22;              // top 10 bits
        int slot;
        for (;;) {
            unsigned int old = atomicCAS(&tab[h], 0xFFFFFFFFu, val);
            if (old == 0xFFFFFFFFu) { slot = h; break; }         // claimed slot
            if ((old >> 9) == uid)  { atomicMin(&tab[h], val); slot = h; break; }
            h = (h + 1) & (HSZ - 1);
        }
        __syncthreads();
        dup = ((tab[slot] & 511u) != (unsigned int)t);
        // dup -> p0 = 1e30 => ex2 argument -> -inf => exact 0 contribution
        spts[t] = make_float2(dup ? 1e30f : (float)(id >> 10), (float)(id & 1023));
    }
    __syncthreads();

    // ---- pass 1: per-cell column sums. warp w owns points [32w,32w+32), lane = cell ----
    {
        const float4 cp = scell[l];
        float c0 = 0.0f, c1 = 0.0f;                 // split the FADD dependency chain
        #pragma unroll
        for (int ii = 0; ii < 32; ii += 2) {
            float2 pa = spts[(w << 5) + ii];
            float2 pb = spts[(w << 5) + ii + 1];
            float a0 = __fmaf_rn(pa.x, cp.x, -cp.z);
            float a1 = __fmaf_rn(pa.y, cp.y, -cp.w);
            float b0 = __fmaf_rn(pb.x, cp.x, -cp.z);
            float b1 = __fmaf_rn(pb.y, cp.y, -cp.w);
            c0 += ex2_approx(__fmaf_rn(-a1, a1, __fmul_rn(-a0, a0)));
            c1 += ex2_approx(__fmaf_rn(-b1, b1, __fmul_rn(-b0, b0)));
        }
        spart[w * CC + l] = c0 + c1;
    }
    __syncthreads();

    // ---- column totals -> value/colsum weights ----
    if (t < CC) {
        float s = 0.0f;
        #pragma unroll
        for (int ww = 0; ww < NWARP; ++ww) s += spart[ww * CC + t];
        svalw[t] = sval[t] / s;
    }
    __syncthreads();

    // ---- pass 2: thread t owns point t; sum over 32 cells, then scatter ----
    {
        const float px = (float)((id >> 10) & 1023);
        const float py = (float)(id & 1023);
        float a0 = 0.0f, a1 = 0.0f;
        #pragma unroll
        for (int c = 0; c < CC; c += 2) {
            float4 ca = scell[c];                   // LDS.128 broadcast
            float4 cb = scell[c + 1];
            float d0 = __fmaf_rn(px, ca.x, -ca.z);
            float d1 = __fmaf_rn(py, ca.y, -ca.w);
            float e0 = __fmaf_rn(px, cb.x, -cb.z);
            float e1 = __fmaf_rn(py, cb.y, -cb.w);
            float wa = ex2_approx(__fmaf_rn(-d1, d1, __fmul_rn(-d0, d0)));
            float wb = ex2_approx(__fmaf_rn(-e1, e1, __fmul_rn(-e0, e0)));
            a0 = __fmaf_rn(wa, svalw[c],     a0);
            a1 = __fmaf_rn(wb, svalw[c + 1], a1);
        }
        if (!dup) {
            const float* xrow = x + b * INSZ;
            float contrib = (a0 + a1) * xrow[id & 1023];
            atomicAdd(&out[b * OUTSZ + ((id >> 10) & 1023)], contrib);
        }
    }
}

extern "C" void kernel_launch(void* const* d_in, const int* in_sizes, int n_in,
                              void* d_out, int out_size)
{
    const float* x      = (const float*)d_in[0];
    const float* means  = (const float*)d_in[1];
    const float* sigmas = (const float*)d_in[2];
    const float* values = (const float*)d_in[3];
    const float* su     = (const float*)d_in[4];
    const float* ru     = (const float*)d_in[5];
    float* out = (float*)d_out;

    cudaMemsetAsync(out, 0, (size_t)out_size * sizeof(float));
    sparse_layer_kernel<<<BB * KK, NP>>>(x, means, sigmas, values, su, ru, out);
}

// round 7
// speedup vs baseline: 1.0136x; 1.0136x over previous
#include <cuda_runtime.h>
#include <math.h>

// Fixed problem shapes: b=8, n=4096, c=32, g=4, rad=4, rank=2, k=128, in=1024, OUT=1024
#define BB    8
#define CC    32
#define GG    4
#define RADR  4
#define KK    128
#define PPC   12          // 4 neighbor + 4 sampled + 4 range-restricted
#define NP    384         // CC * PPC points per (b,k) tile
#define INSZ  1024
#define OUTSZ 1024
#define NWARP 12          // NP/32
#define HSZ   1024        // dup-hash slots (power of 2)
#define NTILES_TOTAL 1024
#define GRID  740         // 148 SMs x 5 resident blocks -> exactly one wave
#define NDBL  (NTILES_TOTAL - GRID)   // 284 blocks run a second tile

// sqrt(0.5 * log2(e)) — folds the -0.5 and exp->exp2 into the inverse sigmas.
#define SQRT_HALF_LOG2E 0.8493218383f

__device__ __forceinline__ float ex2_approx(float v) {
    float r;
    asm("ex2.approx.f32 %0, %1;" : "=f"(r) : "f"(v));
    return r;
}

__global__ __launch_bounds__(NP) void sparse_layer_kernel(
    const float* __restrict__ x,        // (8, 1024)
    const float* __restrict__ means,    // (8, 4096, 2)
    const float* __restrict__ sigmas,   // (8, 4096, 2)
    const float* __restrict__ values,   // (8, 4096)
    const float* __restrict__ su,       // (8, 128, 32, 4, 2)
    const float* __restrict__ ru,       // (8, 128, 32, 4, 2)
    float* __restrict__ out)            // (8, 1024)
{
    // All per-tile state is ping-ponged so tile 1 needs no extra barriers
    // against stragglers still finishing tile 0.
    __shared__ float  sm0[2][CC], sm1[2][CC];
    __shared__ float4 scell[2][CC];         // (v0, v1, m0*v0, m1*v1)
    __shared__ float  sval[2][CC], svalw[2][CC];
    __shared__ float2 spts[2][NP];          // (p0 or 1e30 if dup, p1)
    __shared__ float  spart[2][NWARP * CC];
    __shared__ unsigned int tab[2][HSZ];    // hash: (id<<9)|minidx, EMPTY=~0

    const int bid = blockIdx.x;
    const int t  = threadIdx.x;
    const int w  = t >> 5;
    const int l  = t & 31;

    // ---- init BOTH hash tables up front (covered by the first barrier) ----
    unsigned int* tabflat = &tab[0][0];
    #pragma unroll
    for (int i = t; i < 2 * HSZ; i += NP) tabflat[i] = 0xFFFFFFFFu;

    const int ntiles = (bid < NDBL) ? 2 : 1;

    #pragma unroll 1
    for (int tt = 0; tt < ntiles; ++tt) {
        const int bk = bid + tt * GRID;     // tile id in [0,1024)
        const int b  = bk >> 7;

        // ---- load per-cell params ----
        if (t < CC) {
            int base = (bk * CC + t) * 2;
            float m0 = means[base], m1 = means[base + 1];
            float v0 = sqrtf(1.0f / (1e-6f + sigmas[base]))     * SQRT_HALF_LOG2E;
            float v1 = sqrtf(1.0f / (1e-6f + sigmas[base + 1])) * SQRT_HALF_LOG2E;
            sm0[tt][t] = m0;
            sm1[tt][t] = m1;
            scell[tt][t] = make_float4(v0, v1, m0 * v0, m1 * v1);
            sval[tt][t] = values[bk * CC + t];
        }
        __syncthreads();

        // ---- generate integer tuple: cell c = t/12, slot j ----
        int id;
        {
            const int c = t / PPC;
            const int j = t - c * PPC;
            const float m0v = sm0[tt][c], m1v = sm1[tt][c];
            const float SCL = 1.0f - 1e-6f;
            int i0, i1;
            if (j < 4) {
                // fm order (itertools.product([T,F],2)): True->floor
                i0 = (j & 2) ? (int)ceilf(m0v) : (int)floorf(m0v);
                i1 = (j & 1) ? (int)ceilf(m1v) : (int)floorf(m1v);
            } else if (j < 8) {
                int idx = ((bk * CC + c) * GG + (j - 4)) * 2;
                i0 = (int)floorf(__fmul_rn(__fmul_rn(su[idx],     SCL), 1024.0f));
                i1 = (int)floorf(__fmul_rn(__fmul_rn(su[idx + 1], SCL), 1024.0f));
            } else {
                int idx = ((bk * CC + c) * RADR + (j - 8)) * 2;
                float mn0 = rintf(m0v), mn1 = rintf(m1v);   // round half-even
                float lo0 = mn0 - 8.0f, lo1 = mn1 - 8.0f;
                if (lo0 < 0.0f) lo0 = 0.0f;
                if (mn0 + 8.0f > 1024.0f) lo0 = 1008.0f;
                if (lo1 < 0.0f) lo1 = 0.0f;
                if (mn1 + 8.0f > 1024.0f) lo1 = 1008.0f;
                i0 = (int)floorf(__fadd_rn(__fmul_rn(__fmul_rn(ru[idx],     SCL), 16.0f), lo0));
                i1 = (int)floorf(__fadd_rn(__fmul_rn(__fmul_rn(ru[idx + 1], SCL), 16.0f), lo1));
            }
            id = (i0 << 10) | i1;
        }

        // ---- duplicate marking via shared hash (min thread index wins) ----
        bool dup;
        {
            unsigned int* tb = tab[tt];
            const unsigned int uid = (unsigned int)id;
            const unsigned int val = (uid << 9) | (unsigned int)t;
            unsigned int h = (uid * 2654435761u) >> 22;          // top 10 bits
            int slot;
            for (;;) {
                unsigned int old = atomicCAS(&tb[h], 0xFFFFFFFFu, val);
                if (old == 0xFFFFFFFFu) { slot = h; break; }
                if ((old >> 9) == uid)  { atomicMin(&tb[h], val); slot = h; break; }
                h = (h + 1) & (HSZ - 1);
            }
            __syncthreads();
            dup = ((tb[slot] & 511u) != (unsigned int)t);
            // dup -> p0 = 1e30 => ex2 arg -> -inf => exact 0 contribution
            spts[tt][t] = make_float2(dup ? 1e30f : (float)(id >> 10), (float)(id & 1023));
        }
        __syncthreads();

        // ---- pass 1: per-cell colsum partials. warp w owns its 32 points, lane = cell ----
        {
            const float4 cp = scell[tt][l];
            float c0 = 0.0f, c1 = 0.0f;
            #pragma unroll
            for (int ii = 0; ii < 32; ii += 2) {
                float2 pa = spts[tt][(w << 5) + ii];
                float2 pb = spts[tt][(w << 5) + ii + 1];
                float a0 = __fmaf_rn(pa.x, cp.x, -cp.z);
                float a1 = __fmaf_rn(pa.y, cp.y, -cp.w);
                float b0 = __fmaf_rn(pb.x, cp.x, -cp.z);
                float b1 = __fmaf_rn(pb.y, cp.y, -cp.w);
                c0 += ex2_approx(__fmaf_rn(-a1, a1, __fmul_rn(-a0, a0)));
                c1 += ex2_approx(__fmaf_rn(-b1, b1, __fmul_rn(-b0, b0)));
            }
            spart[tt][w * CC + l] = c0 + c1;
        }
        __syncthreads();

        // ---- column totals -> value/colsum weights ----
        if (t < CC) {
            float s = 0.0f;
            #pragma unroll
            for (int ww = 0; ww < NWARP; ++ww) s += spart[tt][ww * CC + t];
            svalw[tt][t] = sval[tt][t] / s;
        }
        __syncthreads();

        // ---- pass 2: thread t owns point t; sum over 32 cells, scatter ----
        {
            const float px = (float)((id >> 10) & 1023);
            const float py = (float)(id & 1023);
            float a0 = 0.0f, a1 = 0.0f;
            #pragma unroll
            for (int c = 0; c < CC; c += 2) {
                float4 ca = scell[tt][c];               // LDS.128 broadcast
                float4 cb = scell[tt][c + 1];
                float d0 = __fmaf_rn(px, ca.x, -ca.z);
                float d1 = __fmaf_rn(py, ca.y, -ca.w);
                float e0 = __fmaf_rn(px, cb.x, -cb.z);
                float e1 = __fmaf_rn(py, cb.y, -cb.w);
                float wa = ex2_approx(__fmaf_rn(-d1, d1, __fmul_rn(-d0, d0)));
                float wb = ex2_approx(__fmaf_rn(-e1, e1, __fmul_rn(-e0, e0)));
                a0 = __fmaf_rn(wa, svalw[tt][c],     a0);
                a1 = __fmaf_rn(wb, svalw[tt][c + 1], a1);
            }
            if (!dup) {
                float contrib = (a0 + a1) * x[b * INSZ + (id & 1023)];
                atomicAdd(&out[b * OUTSZ + ((id >> 10) & 1023)], contrib);
            }
        }
        // no trailing barrier: next tile uses the other buffer set, and its
        // own first barrier orders the param/tuple stages.
    }
}

extern "C" void kernel_launch(void* const* d_in, const int* in_sizes, int n_in,
                              void* d_out, int out_size)
{
    const float* x      = (const float*)d_in[0];
    const float* means  = (const float*)d_in[1];
    const float* sigmas = (const float*)d_in[2];
    const float* values = (const float*)d_in[3];
    const float* su     = (const float*)d_in[4];
    const float* ru     = (const float*)d_in[5];
    float* out = (float*)d_out;

    cudaMemsetAsync(out, 0, (size_t)out_size * sizeof(float));
    sparse_layer_kernel<<<GRID, NP>>>(x, means, sigmas, values, su, ru, out);
}